// round 7
// baseline (speedup 1.0000x reference)
#include <cuda_runtime.h>
#include <math.h>

// Problem constants
#define NBATCH   64
#define NCH      128
#define NPTS     256           // 16x16 image grid
#define MAPS     32            // BEV map size
#define NCELLS   (MAPS*MAPS)   // 1024
#define HMAXV    14
#define GROUPS   16            // channel groups per batch
#define CH_PER   (NCH / GROUPS)   // 8

__global__ __launch_bounds__(256)
void voxelize_kernel(const float* __restrict__ features,   // (64,128,256)
                     const float* __restrict__ depth,      // (64,1,256)
                     const float* __restrict__ cam,        // (3,256)
                     float* __restrict__ out)              // (64,128,32,32)
{
    __shared__ __align__(16) int   win[NCELLS];            // packed (y<<8)|tid, -1 = empty
    __shared__ __align__(16) float acc[CH_PER * NCELLS];   // 32KB accumulator

    const int tid = threadIdx.x;        // 0..255 == point id
    const int b   = blockIdx.y;         // batch
    const int g   = blockIdx.x;         // channel group
    const int cl4 = tid * 4;            // this thread's 4 cells

    // ---- init shared: win = -1, acc = 0 (all vectorized) ----
    *reinterpret_cast<int4*>(&win[cl4]) = make_int4(-1, -1, -1, -1);
    {
        const float4 z = make_float4(0.f, 0.f, 0.f, 0.f);
        float4* a4 = reinterpret_cast<float4*>(acc);
        #pragma unroll
        for (int i = 0; i < (CH_PER * NCELLS / 4) / 256; i++)
            a4[tid + i * 256] = z;
    }

    // ---- per-point voxel index math (bit-exact vs JAX float32) ----
    const float d  = depth[b * NPTS + tid];
    const float cx = cam[          tid];
    const float cy = cam[  NPTS  + tid];
    const float cz = cam[2*NPTS  + tid];

    const float px = __fmul_rn(d, cx);
    const float py = __fadd_rn(__fmul_rn(d, cy), 1.72f);   // + CAM_HEIGHT
    const float pz = __fmul_rn(d, cz);

    const float CELLF = 0.1f;  // float32(3.2/32)
    const int xi = (int)floorf(__fdiv_rn(px, CELLF)) + (MAPS / 2);
    const int yi = (int)floorf(__fdiv_rn(py, CELLF));
    const int zi = (int)floorf(__fdiv_rn(pz, CELLF)) + MAPS;

    const bool valid = (xi >= 0) & (xi < MAPS) & (zi >= 0) & (zi < MAPS) & (yi < HMAXV);

    // replicate reference flat index semantics: flat = (z*32+x)*14 + y
    // (decompose so negative-y aliasing matches segment_sum behavior exactly)
    int cell = -1, ye = -1;
    if (valid) {
        const int vflat = (zi * MAPS + xi) * HMAXV + yi;
        if (vflat >= 0) {
            cell = vflat / HMAXV;           // ye in [0,13] whenever vflat >= 0
            ye   = vflat - cell * HMAXV;
        }
    }
    __syncthreads();   // init visible

    // ---- phase 1: per-cell winning (highest) voxel y ----
    if (cell >= 0) atomicMax(&win[cell], (ye << 8) | tid);
    __syncthreads();

    // ---- phase 2: contributors scatter-add their features (coalesced LDGs) ----
    const bool contributes = (cell >= 0) && ((win[cell] >> 8) == ye);
    if (contributes) {
        const float* __restrict__ fp =
            features + (size_t)(b * NCH + g * CH_PER) * NPTS + tid;
        #pragma unroll
        for (int c = 0; c < CH_PER; c++)
            atomicAdd(&acc[c * NCELLS + cell], fp[c * NPTS]);
    }
    __syncthreads();

    // ---- phase 3: stream accumulator to output (LDS.128 -> STG.128) ----
    float* __restrict__ ob = out + (size_t)(b * NCH + g * CH_PER) * NCELLS + cl4;
    #pragma unroll
    for (int c = 0; c < CH_PER; c++) {
        *reinterpret_cast<float4*>(ob + c * NCELLS) =
            *reinterpret_cast<const float4*>(&acc[c * NCELLS + cl4]);
    }
}

extern "C" void kernel_launch(void* const* d_in, const int* in_sizes, int n_in,
                              void* d_out, int out_size)
{
    const float* features = (const float*)d_in[0];   // 64*128*16*16
    const float* depth    = (const float*)d_in[1];   // 64*1*16*16
    const float* cam      = (const float*)d_in[2];   // 3*256
    float*       out      = (float*)d_out;           // 64*128*32*32

    dim3 grid(GROUPS, NBATCH);
    voxelize_kernel<<<grid, 256>>>(features, depth, cam, out);
}

// round 9
// speedup vs baseline: 1.3107x; 1.3107x over previous
#include <cuda_runtime.h>
#include <math.h>

// Problem constants
#define NBATCH   64
#define NCH      128
#define NPTS     256           // 16x16 image grid
#define MAPS     32            // BEV map size
#define NCELLS   (MAPS*MAPS)   // 1024
#define HMAXV    14
#define GROUPS   16            // channel groups per batch
#define CH_PER   (NCH / GROUPS)   // 8

__global__ __launch_bounds__(256)
void voxelize_kernel(const float* __restrict__ features,   // (64,128,256)
                     const float* __restrict__ depth,      // (64,1,256)
                     const float* __restrict__ cam,        // (3,256)
                     float* __restrict__ out)              // (64,128,32,32)
{
    __shared__ __align__(16) int win[NCELLS];   // packed (y<<8)|tid, -1 = empty (4KB)

    const int tid = threadIdx.x;        // 0..255 == point id
    const int b   = blockIdx.y;         // batch
    const int g   = blockIdx.x;         // channel group
    const int cl4 = tid * 4;            // this thread's 4 cells

    // ---- init winner table ----
    *reinterpret_cast<int4*>(&win[cl4]) = make_int4(-1, -1, -1, -1);

    // ---- zero-fill this block's output slab EARLY (coalesced STG.128,
    //      overlaps with prologue math/atomics; ordered before REDs by barrier 2)
    float* __restrict__ ob = out + (size_t)(b * NCH + g * CH_PER) * NCELLS;
    {
        const float4 z = make_float4(0.f, 0.f, 0.f, 0.f);
        #pragma unroll
        for (int c = 0; c < CH_PER; c++)
            *reinterpret_cast<float4*>(ob + c * NCELLS + cl4) = z;
    }

    // ---- per-point voxel index math (bit-exact vs JAX float32) ----
    const float d  = depth[b * NPTS + tid];
    const float cx = cam[          tid];
    const float cy = cam[  NPTS  + tid];
    const float cz = cam[2*NPTS  + tid];

    const float px = __fmul_rn(d, cx);
    const float py = __fadd_rn(__fmul_rn(d, cy), 1.72f);   // + CAM_HEIGHT
    const float pz = __fmul_rn(d, cz);

    const float CELLF = 0.1f;  // float32(3.2/32)
    const int xi = (int)floorf(__fdiv_rn(px, CELLF)) + (MAPS / 2);
    const int yi = (int)floorf(__fdiv_rn(py, CELLF));
    const int zi = (int)floorf(__fdiv_rn(pz, CELLF)) + MAPS;

    const bool valid = (xi >= 0) & (xi < MAPS) & (zi >= 0) & (zi < MAPS) & (yi < HMAXV);

    // replicate reference flat index semantics: flat = (z*32+x)*14 + y
    // (decompose so negative-y aliasing matches segment_sum behavior exactly)
    int cell = -1, ye = -1;
    if (valid) {
        const int vflat = (zi * MAPS + xi) * HMAXV + yi;
        if (vflat >= 0) {
            cell = vflat / HMAXV;
            ye   = vflat - cell * HMAXV;
        }
    }
    __syncthreads();   // barrier 1: win init visible

    // ---- phase 1: per-cell winning (highest) voxel ----
    if (cell >= 0) atomicMax(&win[cell], (ye << 8) | tid);
    __syncthreads();   // barrier 2: winners final + zero-fill ordered before REDs

    // ---- phase 2: contributors RED their features into the zeroed slab ----
    if (cell >= 0 && (win[cell] >> 8) == ye) {
        const float* __restrict__ fp =
            features + (size_t)(b * NCH + g * CH_PER) * NPTS + tid;
        #pragma unroll
        for (int c = 0; c < CH_PER; c++)
            atomicAdd(&ob[c * NCELLS + cell], fp[c * NPTS]);   // REDG, no return
    }
}

extern "C" void kernel_launch(void* const* d_in, const int* in_sizes, int n_in,
                              void* d_out, int out_size)
{
    const float* features = (const float*)d_in[0];   // 64*128*16*16
    const float* depth    = (const float*)d_in[1];   // 64*1*16*16
    const float* cam      = (const float*)d_in[2];   // 3*256
    float*       out      = (float*)d_out;           // 64*128*32*32

    dim3 grid(GROUPS, NBATCH);
    voxelize_kernel<<<grid, 256>>>(features, depth, cam, out);
}